// round 11
// baseline (speedup 1.0000x reference)
#include <cuda_runtime.h>

// PixelRNN: 2-layer LSTM, T=4096 steps, B=256, H=128, OUT=45.
// Persistent cooperative kernel, layer-split warp specialization:
//   tid 0..255  : layer-0 partial GEMM (k-eighth per warp, 2 batch rows/lane)
//                 + out-proj half-dots + combine/epilogue (c-state here)
//   tid 256..511: layer-1 partial GEMM + final out-proj adds
// Each weight row broadcast-loaded by exactly one warp (w-wavefronts
// unchanged vs R10) but warps/SMSP doubles 2->4 to hide LDS/L2 latency.
// Partials exchanged via conflict-free [slot][bl] smem. Proven barrier.
// Co-residency: 128 CTAs, ~181KB dyn smem -> 1 CTA/SM, wave-1 resident.

#define TSEQ   4096
#define BATCH  256
#define HSZ    128
#define NOUT   45
#define NCTA   128     // 4 batch tiles x 32 u-groups
#define NTH    512
#define BTILE  64      // batch rows per CTA
#define UPG    4       // hidden units per CTA

typedef unsigned long long ull;

// ---- persistent device state ----
__device__ float g_h0T[2 * HSZ * BATCH];   // [parity][k][b]
__device__ float g_h1T[2 * HSZ * BATCH];
__device__ float g_Mf[512 * 4];            // folded input path: [j][c0,c1,c2,bias0]
__device__ float g_bias1[512];
__device__ unsigned int g_bar;

__global__ void prep_kernel(const float* __restrict__ W_in, const float* __restrict__ b_in,
                            const float* __restrict__ W_ih, const float* __restrict__ b_ih,
                            const float* __restrict__ b_hh) {
    int idx = blockIdx.x * blockDim.x + threadIdx.x;
    int stride = gridDim.x * blockDim.x;
    for (int i = idx; i < 2 * HSZ * BATCH; i += stride) {
        g_h0T[i] = 0.f;
        g_h1T[i] = 0.f;
    }
    if (idx == 0) g_bar = 0u;
    int j = idx;
    if (j < 512) {
        float m0 = 0.f, m1 = 0.f, m2 = 0.f, mb = 0.f;
        for (int k = 0; k < HSZ; ++k) {
            float w = W_ih[j * HSZ + k];             // layer 0
            m0 += w * W_in[k * 3 + 0];
            m1 += w * W_in[k * 3 + 1];
            m2 += w * W_in[k * 3 + 2];
            mb += w * b_in[k];
        }
        g_Mf[j * 4 + 0] = m0;
        g_Mf[j * 4 + 1] = m1;
        g_Mf[j * 4 + 2] = m2;
        g_Mf[j * 4 + 3] = mb + b_ih[j] + b_hh[j];
        g_bias1[j] = b_ih[512 + j] + b_hh[512 + j];
    }
}

__device__ __forceinline__ float sigf(float v)  { return 1.0f / (1.0f + __expf(-v)); }
__device__ __forceinline__ float tanh_(float v) { return 1.0f - 2.0f / (__expf(2.0f * v) + 1.0f); }

__device__ __forceinline__ ull pack2(float lo, float hi) {
    ull r;
    asm("mov.b64 %0, {%1, %2};" : "=l"(r) : "f"(lo), "f"(hi));
    return r;
}
__device__ __forceinline__ ull packdup(float v) {
    ull r;
    asm("mov.b64 %0, {%1, %1};" : "=l"(r) : "f"(v));
    return r;
}
__device__ __forceinline__ void fma2(ull& acc, ull a, ull b) {
    asm("fma.rn.f32x2 %0, %1, %2, %0;" : "+l"(acc) : "l"(a), "l"(b));
}
__device__ __forceinline__ void add2(ull& acc, ull a) {
    asm("add.rn.f32x2 %0, %0, %1;" : "+l"(acc) : "l"(a));
}
__device__ __forceinline__ void unpack2(float& lo, float& hi, ull v) {
    asm("mov.b64 {%0, %1}, %2;" : "=f"(lo), "=f"(hi) : "l"(v));
}

// SMEM layout (floats)
#define SM_H0S   0                   // [128][64]   h0_{s-1}
#define SM_H1S   8192                // [128][64]   h1_{s-2}
#define SM_W0S   16384               // [128][16]   layer0 Whh slice [k][ul*4+g]
#define SM_W1S   18432               // [128][32]   layer1 [k][ul*8 + mat*4 + g]
#define SM_WOT   22528               // [128][48]   W_out^T padded
#define SM_BO    28672               // [48]
#define SM_OPART 28720               // [192]       out-proj half-dot partials
#define SM_PART  28912               // 8192 ull: partials [(u*4+g2)*8 + w][bl]
#define SM_FLOATS (28912 + 8192 * 2)
#define SMEM_BYTES (SM_FLOATS * 4)

__global__ void __launch_bounds__(NTH, 1) lstm_persist(
    const float* __restrict__ x,      // [B,3,64,64]
    const float* __restrict__ W_ih,   // [2,512,128]
    const float* __restrict__ W_hh,   // [2,512,128]
    const float* __restrict__ W_out,  // [45,128]
    const float* __restrict__ b_out,  // [45]
    float* __restrict__ out)          // [B,T,45]
{
    extern __shared__ float sm[];
    float* h0s = sm + SM_H0S;
    float* h1s = sm + SM_H1S;
    float* W0s = sm + SM_W0S;
    float* W1s = sm + SM_W1S;
    float* WoT = sm + SM_WOT;
    float* bo  = sm + SM_BO;
    float* opart = sm + SM_OPART;
    ull* part = reinterpret_cast<ull*>(sm + SM_PART);

    const int tid = threadIdx.x;
    const int bt = blockIdx.x & 3;
    const int ug = blockIdx.x >> 2;        // 0..31
    const int b0 = bt * BTILE;
    const int uStart = ug * UPG;

    // ---- one-time weight staging ----
    for (int i = tid; i < 16 * HSZ; i += NTH) {
        int colg = i >> 7, k = i & 127;            // colg = ul*4+g
        int ul_ = colg >> 2, g = colg & 3;
        W0s[k * 16 + colg] = __ldg(&W_hh[(uStart + ul_ + g * HSZ) * HSZ + k]);  // layer0 hh
    }
    for (int i = tid; i < 32 * HSZ; i += NTH) {
        int col = i >> 7, k = i & 127;             // col = ul*8 + mat*4 + g
        int ul_ = col >> 3, mt = (col >> 2) & 1, g = col & 3;
        const float* src = mt ? (W_hh + 512 * HSZ) : (W_ih + 512 * HSZ);
        W1s[k * 32 + col] = __ldg(&src[(uStart + ul_ + g * HSZ) * HSZ + k]);
    }
    for (int i = tid; i < NOUT * HSZ; i += NTH) {
        int o = i >> 7, k = i & 127;
        WoT[k * 48 + o] = __ldg(&W_out[o * HSZ + k]);
    }
    if (tid < NOUT) bo[tid] = __ldg(&b_out[tid]);
    __syncthreads();

    const bool lo = (tid < 256);
    const int gw   = (tid >> 5) & 7;       // gemm warp within half (k-eighth)
    const int lane = tid & 31;
    const int kb   = gw * 16;

    // combine role (lower half): cell (bl, ul)
    const int bl = tid & 63;
    const int ul = (tid >> 6) & 3;
    const int b  = b0 + bl;
    const int u  = uStart + ul;

    // out-proj half-dot role (lower half, tid < 180): pair p2, k-half kh
    const int p2 = tid >> 1;
    const int kh = (tid & 1) * 64;
    const int d1   = ug * 90 + p2;
    const int ob1  = d1 / 45;
    const int oo1  = d1 - ob1 * 45;
    // out-proj final role (upper half, utid = tid-256 < 90)
    const int utid = tid - 256;
    const int d2   = ug * 90 + (utid >= 0 ? utid : 0);
    const int ob2  = d2 / 45;
    const int oo2  = d2 - ob2 * 45;

    float c0r = 0.f, c1r = 0.f;   // cell states (lower half, per (bl,ul))

    const float4 mi = *reinterpret_cast<const float4*>(&g_Mf[(u        ) * 4]);
    const float4 mf = *reinterpret_cast<const float4*>(&g_Mf[(u + 128) * 4]);
    const float4 mg = *reinterpret_cast<const float4*>(&g_Mf[(u + 256) * 4]);
    const float4 mo = *reinterpret_cast<const float4*>(&g_Mf[(u + 384) * 4]);
    const ull bIF1 = pack2(g_bias1[u],       g_bias1[u + 128]);
    const ull bGO1 = pack2(g_bias1[u + 256], g_bias1[u + 384]);

    const float* xrow = x + b * 3 * TSEQ;

    for (int s = 0; s <= TSEQ + 1; ++s) {
        const int rp  = (s + 1) & 1;   // == (s-1)&1 : h0 prev parity
        const int rp2 = s & 1;         // == (s-2)&1 : h1 prev parity

        // prefetch pixel early (combine role = lower half)
        float px0 = 0.f, px1 = 0.f, px2 = 0.f;
        if (lo && s < TSEQ) {
            px0 = __ldg(xrow + s);
            px1 = __ldg(xrow + TSEQ + s);
            px2 = __ldg(xrow + 2 * TSEQ + s);
        }

        // ---- stage h0_{s-1} and h1_{s-2} slices into SMEM (512 threads)
        for (int i = tid; i < HSZ * 16; i += NTH) {
            int k = i >> 4, c = i & 15;
            float4 v0 = __ldcg(reinterpret_cast<const float4*>(&g_h0T[(rp  * HSZ + k) * BATCH + b0]) + c);
            reinterpret_cast<float4*>(h0s)[i] = v0;
            float4 v1 = __ldcg(reinterpret_cast<const float4*>(&g_h1T[(rp2 * HSZ + k) * BATCH + b0]) + c);
            reinterpret_cast<float4*>(h1s)[i] = v1;
        }
        __syncthreads();

        // ---- partial GEMM over this warp's k-eighth, 2 batch rows/lane.
        //      Lower half: layer 0. Upper half: layer 1. Runs unconditionally
        //      (h buffers zero at edges; results gated at epilogue).
        ull aIF[UPG] = {0,0,0,0}, aGO[UPG] = {0,0,0,0};
        ull bIF[UPG] = {0,0,0,0}, bGO[UPG] = {0,0,0,0};

        if (lo) {
            const float* h0p = h0s + kb * 64;
            #pragma unroll 4
            for (int k = 0; k < 16; ++k) {
                const float* hr0 = h0p + k * 64;
                ull h0a = packdup(hr0[lane]);
                ull h0b = packdup(hr0[lane + 32]);
                const ulonglong2* w0r = reinterpret_cast<const ulonglong2*>(W0s + (kb + k) * 16);
                #pragma unroll
                for (int uu = 0; uu < UPG; ++uu) {
                    ulonglong2 w0 = w0r[uu];
                    fma2(aIF[uu], h0a, w0.x); fma2(aGO[uu], h0a, w0.y);
                    fma2(bIF[uu], h0b, w0.x); fma2(bGO[uu], h0b, w0.y);
                }
            }
        } else {
            const float* h0p = h0s + kb * 64;
            const float* h1p = h1s + kb * 64;
            #pragma unroll 4
            for (int k = 0; k < 16; ++k) {
                const float* hr0 = h0p + k * 64;
                const float* hr1 = h1p + k * 64;
                ull h0a = packdup(hr0[lane]);
                ull h0b = packdup(hr0[lane + 32]);
                ull h1a = packdup(hr1[lane]);
                ull h1b = packdup(hr1[lane + 32]);
                const ulonglong2* w1r = reinterpret_cast<const ulonglong2*>(W1s + (kb + k) * 32);
                #pragma unroll
                for (int uu = 0; uu < UPG; ++uu) {
                    ulonglong2 wi = w1r[2 * uu];
                    ulonglong2 wh = w1r[2 * uu + 1];
                    fma2(aIF[uu], h0a, wi.x); fma2(aGO[uu], h0a, wi.y);
                    fma2(aIF[uu], h1a, wh.x); fma2(aGO[uu], h1a, wh.y);
                    fma2(bIF[uu], h0b, wi.x); fma2(bGO[uu], h0b, wi.y);
                    fma2(bIF[uu], h1b, wh.x); fma2(bGO[uu], h1b, wh.y);
                }
            }
        }

        // ---- out-projection half-dot (step s-2), lower 180 threads
        float oacc = 0.f;
        if (s >= 2 && tid < 180) {
            const float* hp  = h1s + kh * 64 + ob1;
            const float* wpo = WoT + kh * 48 + oo1;
            #pragma unroll 8
            for (int k = 0; k < 64; ++k) {
                oacc += (*hp) * (*wpo);
                hp += 64; wpo += 48;
            }
        }

        // ---- store partials: part[(u*4+g2)*8 + w][bl]
        //      lower stores g2 0,1 (layer0 IF/GO); upper stores g2 2,3.
        {
            const int g2a = lo ? 0 : 2;
            #pragma unroll
            for (int uu = 0; uu < UPG; ++uu) {
                ull* r0 = part + ((uu * 4 + g2a    ) * 8 + gw) * 64;
                ull* r1 = part + ((uu * 4 + g2a + 1) * 8 + gw) * 64;
                r0[lane] = aIF[uu];  r0[lane + 32] = bIF[uu];
                r1[lane] = aGO[uu];  r1[lane + 32] = bGO[uu];
            }
            if (s >= 2 && tid < 180) opart[tid] = oacc;
        }
        __syncthreads();

        if (lo) {
            // ---- combine + epilogue: this thread owns cell (bl, ul)
            ull s0 = 0, s1 = 0, s2 = 0, s3 = 0;
            #pragma unroll
            for (int w = 0; w < 8; ++w) {
                add2(s0, part[((ul * 4 + 0) * 8 + w) * 64 + bl]);
                add2(s1, part[((ul * 4 + 1) * 8 + w) * 64 + bl]);
                add2(s2, part[((ul * 4 + 2) * 8 + w) * 64 + bl]);
                add2(s3, part[((ul * 4 + 3) * 8 + w) * 64 + bl]);
            }

            // layer 0 epilogue, step s
            if (s < TSEQ) {
                float ai, af, ag, ao;
                unpack2(ai, af, s0);
                unpack2(ag, ao, s1);
                ai += mi.x * px0 + mi.y * px1 + mi.z * px2 + mi.w;
                af += mf.x * px0 + mf.y * px1 + mf.z * px2 + mf.w;
                ag += mg.x * px0 + mg.y * px1 + mg.z * px2 + mg.w;
                ao += mo.x * px0 + mo.y * px1 + mo.z * px2 + mo.w;
                float I = sigf(ai), F = sigf(af), G = tanh_(ag), O = sigf(ao);
                c0r = F * c0r + I * G;
                float h = O * tanh_(c0r);
                __stcg(&g_h0T[((s & 1) * HSZ + u) * BATCH + b], h);
            }
            // layer 1 epilogue, step s-1
            if (s >= 1 && s <= TSEQ) {
                add2(s2, bIF1);
                add2(s3, bGO1);
                float ai, af, ag, ao;
                unpack2(ai, af, s2);
                unpack2(ag, ao, s3);
                float I = sigf(ai), F = sigf(af), G = tanh_(ag), O = sigf(ao);
                c1r = F * c1r + I * G;
                float h = O * tanh_(c1r);
                __stcg(&g_h1T[(((s - 1) & 1) * HSZ + u) * BATCH + b], h);
            }
        } else {
            // ---- out-projection final add (step s-2), upper 90 threads
            if (s >= 2 && utid < 90) {
                float acc = opart[2 * utid] + opart[2 * utid + 1] + bo[oo2];
                out[(b0 + ob2) * (TSEQ * NOUT) + (s - 2) * NOUT + oo2] = acc;
            }
        }

        // ---- global barrier (proven): atomicAdd + fence + volatile spin
        __syncthreads();
        if (tid == 0) {
            __threadfence();
            atomicAdd(&g_bar, 1u);
            const unsigned target = (unsigned)(s + 1) * (unsigned)NCTA;
            while (*reinterpret_cast<volatile unsigned*>(&g_bar) < target) {
                __nanosleep(64);
            }
            __threadfence();
        }
        __syncthreads();
    }
}

extern "C" void kernel_launch(void* const* d_in, const int* in_sizes, int n_in,
                              void* d_out, int out_size) {
    const float* x     = (const float*)d_in[0];
    const float* W_in  = (const float*)d_in[1];
    const float* b_in  = (const float*)d_in[2];
    const float* W_ih  = (const float*)d_in[3];
    const float* W_hh  = (const float*)d_in[4];
    const float* b_ih  = (const float*)d_in[5];
    const float* b_hh  = (const float*)d_in[6];
    const float* W_out = (const float*)d_in[7];
    const float* b_out = (const float*)d_in[8];
    float* out = (float*)d_out;

    cudaFuncSetAttribute(lstm_persist, cudaFuncAttributeMaxDynamicSharedMemorySize, SMEM_BYTES);

    prep_kernel<<<64, 256>>>(W_in, b_in, W_ih, b_ih, b_hh);
    lstm_persist<<<NCTA, NTH, SMEM_BYTES>>>(x, W_ih, W_hh, W_out, b_out, out);
}